// round 10
// baseline (speedup 1.0000x reference)
#include <cuda_runtime.h>
#include <cuda_bf16.h>

#define B_  16
#define S_  2048
#define D_  128
#define BQ  128
#define BK  64
#define NT  512
#define NTILES (S_/BK)

#define STR  272             // Q/K/V smem row stride (bytes): 128 bf16 + 8 pad
#define PSTR 144             // P smem row stride (bytes): 64 bf16 + 8 pad

#define OFF_QH 0
#define OFF_QL 34816
#define OFF_KH 69632
#define OFF_KL 87040
#define OFF_VH 104448
#define OFF_VL 121856
#define OFF_PH 139264        // P hi: 128 x 144
#define OFF_PL 157696        // P lo: 128 x 144
#define OFF_KPM 176128       // 64 B + pad
#define OFF_L2  176256       // 2 x 128 floats
#define SMEM_BYTES (176256 + 1024)

__device__ __forceinline__ unsigned smem_u32(const void* p) {
    unsigned a;
    asm("{ .reg .u64 t; cvta.to.shared.u64 t, %1; cvt.u32.u64 %0, t; }" : "=r"(a) : "l"(p));
    return a;
}

#define LDSM_X4(r0,r1,r2,r3,a) \
    asm("ldmatrix.sync.aligned.m8n8.x4.shared.b16 {%0,%1,%2,%3}, [%4];" \
        : "=r"(r0),"=r"(r1),"=r"(r2),"=r"(r3) : "r"(a) : "memory")
#define LDSM_X4T(r0,r1,r2,r3,a) \
    asm("ldmatrix.sync.aligned.m8n8.x4.trans.shared.b16 {%0,%1,%2,%3}, [%4];" \
        : "=r"(r0),"=r"(r1),"=r"(r2),"=r"(r3) : "r"(a) : "memory")

#define MMA(c,a0,a1,a2,a3,b0,b1) \
    asm("mma.sync.aligned.m16n8k16.row.col.f32.bf16.bf16.f32 " \
        "{%0,%1,%2,%3}, {%4,%5,%6,%7}, {%8,%9}, {%0,%1,%2,%3};" \
        : "+f"((c)[0]),"+f"((c)[1]),"+f"((c)[2]),"+f"((c)[3]) \
        : "r"(a0),"r"(a1),"r"(a2),"r"(a3),"r"(b0),"r"(b1))

__device__ __forceinline__ unsigned pack2(float x, float y) {
    __nv_bfloat162 h = __floats2bfloat162_rn(x, y);   // x -> low half
    return *reinterpret_cast<unsigned*>(&h);
}

__device__ __forceinline__ void split2(float x, float y, unsigned& hi, unsigned& lo) {
    __nv_bfloat16 hx = __float2bfloat16(x), hy = __float2bfloat16(y);
    float lx = x - __bfloat162float(hx);
    float ly = y - __bfloat162float(hy);
    __nv_bfloat162 hp; hp.x = hx; hp.y = hy;
    hi = *reinterpret_cast<unsigned*>(&hp);
    lo = pack2(lx, ly);
}

// cooperative load of [rows][128] f32 tile -> split bf16 hi/lo smem (stride 272B)
template<int ROWS>
__device__ __forceinline__ void load_split(char* smc, const float* g, int offH, int offL, float mul) {
    const float4* g4 = reinterpret_cast<const float4*>(g);
    #pragma unroll
    for (int it = 0; it < (ROWS * 32) / NT; ++it) {
        int idx = threadIdx.x + it * NT;
        int r = idx >> 5, c4 = idx & 31;
        float4 v = g4[idx];
        unsigned h0, l0, h1, l1;
        split2(v.x * mul, v.y * mul, h0, l0);
        split2(v.z * mul, v.w * mul, h1, l1);
        unsigned off = (unsigned)(r * STR + c4 * 8);
        *reinterpret_cast<uint2*>(smc + offH + off) = make_uint2(h0, h1);
        *reinterpret_cast<uint2*>(smc + offL + off) = make_uint2(l0, l1);
    }
}

__global__ __launch_bounds__(NT, 1)
void fa_mma_kernel(const float* __restrict__ Q, const float* __restrict__ K,
                   const float* __restrict__ V, const unsigned char* __restrict__ kpm,
                   const int* __restrict__ cls, float* __restrict__ O)
{
    extern __shared__ char smc[];
    const unsigned sb = smem_u32(smc);
    const int tid  = threadIdx.x;
    const int wid  = tid >> 5;
    const int lane = tid & 31;
    const int rg   = wid >> 1;       // row-group 0..7 (16 q-rows each)
    const int h    = wid & 1;        // key-half (QK) / dcol-half (PV)
    const int b  = blockIdx.y;
    const int q0 = blockIdx.x * BQ;

    const int i0 = cls[b*3 + 0];
    const int i1 = cls[b*3 + 1];
    const int i2 = cls[b*3 + 2];

    const int lrow0 = rg*16 + (lane >> 2);   // local q-row of fragment row pair
    const int rg0 = q0 + lrow0;
    const int rg1 = rg0 + 8;
    const bool isr1_0 = (rg0 == i1), isr2_0 = (rg0 == i2);
    const bool isr1_1 = (rg1 == i1), isr2_1 = (rg1 == i2);

    load_split<BQ>(smc, Q + ((size_t)b*S_ + q0)*D_, OFF_QH, OFF_QL, 0.08838834764831845f);

    float o[8][4];
    #pragma unroll
    for (int i = 0; i < 8; ++i)
        #pragma unroll
        for (int j = 0; j < 4; ++j) o[i][j] = 0.0f;
    float lacc0 = 0.0f, lacc1 = 0.0f;

    // ldmatrix lane addressing
    const unsigned qrow_off = (unsigned)((rg*16 + (lane & 15)) * STR) + ((lane >> 4) ? 16u : 0u);
    const unsigned krow     = (unsigned)((((lane >> 4) & 1) * 8 + (lane & 7)) * STR) + (((lane >> 3) & 1) ? 16u : 0u);
    const unsigned vrow     = (unsigned)(((((lane >> 3) & 1) * 8) + (lane & 7)) * STR) + ((lane >> 4) ? 16u : 0u);
    const unsigned prow_off = (unsigned)((rg*16 + (lane & 15)) * PSTR) + ((lane >> 4) ? 16u : 0u);

    for (int tl = 0; tl < NTILES; ++tl) {
        const int kb = tl * BK;
        __syncthreads();   // previous tile's K/V/P readers done

        load_split<BK>(smc, K + ((size_t)b*S_ + kb)*D_, OFF_KH, OFF_KL, 1.0f);
        load_split<BK>(smc, V + ((size_t)b*S_ + kb)*D_, OFF_VH, OFF_VL, 1.0f);
        if (tid < 16) ((unsigned*)(smc + OFF_KPM))[tid] = ((const unsigned*)(kpm + (size_t)b*S_ + kb))[tid];
        __syncthreads();

        // ---- QK^T : 16 rows x 32 keys per warp, split-2 ----
        float s[4][4];
        #pragma unroll
        for (int i = 0; i < 4; ++i)
            #pragma unroll
            for (int j = 0; j < 4; ++j) s[i][j] = 0.0f;

        #pragma unroll
        for (int ks = 0; ks < 8; ++ks) {
            const unsigned kbyte = (unsigned)(ks * 32);
            unsigned aqh[4], aql[4];
            LDSM_X4(aqh[0], aqh[1], aqh[2], aqh[3], sb + OFF_QH + qrow_off + kbyte);
            LDSM_X4(aql[0], aql[1], aql[2], aql[3], sb + OFF_QL + qrow_off + kbyte);
            #pragma unroll
            for (int np = 0; np < 2; ++np) {    // keys (h*32 + np*16) .. +16
                unsigned roff = (unsigned)((h*32 + np*16) * STR) + krow + kbyte;
                unsigned bh0, bh1, bh2, bh3, bl0, bl1, bl2, bl3;
                LDSM_X4(bh0, bh1, bh2, bh3, sb + OFF_KH + roff);
                MMA(s[2*np],   aqh[0], aqh[1], aqh[2], aqh[3], bh0, bh1);
                MMA(s[2*np+1], aqh[0], aqh[1], aqh[2], aqh[3], bh2, bh3);
                MMA(s[2*np],   aql[0], aql[1], aql[2], aql[3], bh0, bh1);
                MMA(s[2*np+1], aql[0], aql[1], aql[2], aql[3], bh2, bh3);
                LDSM_X4(bl0, bl1, bl2, bl3, sb + OFF_KL + roff);
                MMA(s[2*np],   aqh[0], aqh[1], aqh[2], aqh[3], bl0, bl1);
                MMA(s[2*np+1], aqh[0], aqh[1], aqh[2], aqh[3], bl2, bl3);
            }
        }

        // ---- mask + exp + split + store P to smem ----
        const unsigned char* kpms = (const unsigned char*)(smc + OFF_KPM);
        #pragma unroll
        for (int nt = 0; nt < 4; ++nt) {
            const int jl0 = h*32 + nt*8 + (lane & 3)*2;
            const int jg0 = kb + jl0, jg1 = jg0 + 1;
            const bool kp0 = kpms[jl0] != 0, kp1 = kpms[jl0 + 1] != 0;
            const bool key1_0 = ((jg0 > i1) && (jg0 <= i2)) || (jg0 == 0);
            const bool key1_1 = ((jg1 > i1) && (jg1 <= i2)) || (jg1 == 0);
            const bool key2_0 = ((jg0 > i0) && (jg0 <= i1)) || (jg0 == 0);
            const bool key2_1 = ((jg1 > i0) && (jg1 <= i1)) || (jg1 == 0);

            float v0 = (kp0 || (isr1_0 && key1_0) || (isr2_0 && key2_0)) ? -1e30f : s[nt][0];
            float v1 = (kp1 || (isr1_0 && key1_1) || (isr2_0 && key2_1)) ? -1e30f : s[nt][1];
            float v2 = (kp0 || (isr1_1 && key1_0) || (isr2_1 && key2_0)) ? -1e30f : s[nt][2];
            float v3 = (kp1 || (isr1_1 && key1_1) || (isr2_1 && key2_1)) ? -1e30f : s[nt][3];

            float p0 = __expf(fminf(v0, 60.0f));
            float p1 = __expf(fminf(v1, 60.0f));
            float p2 = __expf(fminf(v2, 60.0f));
            float p3 = __expf(fminf(v3, 60.0f));
            lacc0 += p0 + p1;
            lacc1 += p2 + p3;

            unsigned h01, l01, h23, l23;
            split2(p0, p1, h01, l01);
            split2(p2, p3, h23, l23);
            const unsigned cb = (unsigned)(jl0 * 2);        // byte offset of key col
            const unsigned r0off = (unsigned)(lrow0 * PSTR) + cb;
            const unsigned r1off = r0off + (unsigned)(8 * PSTR);
            *reinterpret_cast<unsigned*>(smc + OFF_PH + r0off) = h01;
            *reinterpret_cast<unsigned*>(smc + OFF_PL + r0off) = l01;
            *reinterpret_cast<unsigned*>(smc + OFF_PH + r1off) = h23;
            *reinterpret_cast<unsigned*>(smc + OFF_PL + r1off) = l23;
        }
        __syncthreads();   // full 64-key P visible to both warps of each row-group

        // ---- P·V : 16 rows x 64 dcols (half h) per warp, split-2 ----
        #pragma unroll
        for (int ks = 0; ks < 4; ++ks) {       // keys in steps of 16
            const unsigned pко = (unsigned)(ks * 32);
            unsigned aph[4], apl[4];
            LDSM_X4(aph[0], aph[1], aph[2], aph[3], sb + OFF_PH + prow_off + pко);
            LDSM_X4(apl[0], apl[1], apl[2], apl[3], sb + OFF_PL + prow_off + pко);
            const unsigned krow_off = (unsigned)(ks * 16 * STR) + vrow;
            #pragma unroll
            for (int dp = 0; dp < 4; ++dp) {   // dcols h*64 + dp*16
                unsigned off = krow_off + (unsigned)((h*64 + dp*16) * 2);
                unsigned bh0, bh1, bh2, bh3, bl0, bl1, bl2, bl3;
                LDSM_X4T(bh0, bh1, bh2, bh3, sb + OFF_VH + off);
                MMA(o[2*dp],   aph[0], aph[1], aph[2], aph[3], bh0, bh1);
                MMA(o[2*dp+1], aph[0], aph[1], aph[2], aph[3], bh2, bh3);
                MMA(o[2*dp],   apl[0], apl[1], apl[2], apl[3], bh0, bh1);
                MMA(o[2*dp+1], apl[0], apl[1], apl[2], apl[3], bh2, bh3);
                LDSM_X4T(bl0, bl1, bl2, bl3, sb + OFF_VL + off);
                MMA(o[2*dp],   aph[0], aph[1], aph[2], aph[3], bl0, bl1);
                MMA(o[2*dp+1], aph[0], aph[1], aph[2], aph[3], bl2, bl3);
            }
        }
    }

    // ---- final: combine l across warp pair, normalize, store ----
    lacc0 += __shfl_xor_sync(0xffffffffu, lacc0, 1);
    lacc0 += __shfl_xor_sync(0xffffffffu, lacc0, 2);
    lacc1 += __shfl_xor_sync(0xffffffffu, lacc1, 1);
    lacc1 += __shfl_xor_sync(0xffffffffu, lacc1, 2);
    float* l2 = (float*)(smc + OFF_L2);
    if ((lane & 3) == 0) {
        l2[h*128 + lrow0]     = lacc0;
        l2[h*128 + lrow0 + 8] = lacc1;
    }
    __syncthreads();
    const float inv0 = 1.0f / (l2[lrow0]     + l2[128 + lrow0]);
    const float inv1 = 1.0f / (l2[lrow0 + 8] + l2[128 + lrow0 + 8]);

    float* O0 = O + ((size_t)b*S_ + rg0)*D_;
    float* O1 = O + ((size_t)b*S_ + rg1)*D_;
    #pragma unroll
    for (int dp = 0; dp < 4; ++dp) {
        #pragma unroll
        for (int half = 0; half < 2; ++half) {
            const int col = h*64 + dp*16 + half*8 + (lane & 3)*2;
            const int ci = 2*dp + half;
            float2 w0 = make_float2(o[ci][0]*inv0, o[ci][1]*inv0);
            float2 w1 = make_float2(o[ci][2]*inv1, o[ci][3]*inv1);
            *reinterpret_cast<float2*>(O0 + col) = w0;
            *reinterpret_cast<float2*>(O1 + col) = w1;
        }
    }
}

extern "C" void kernel_launch(void* const* d_in, const int* in_sizes, int n_in,
                              void* d_out, int out_size)
{
    const float* Q = (const float*)d_in[0];
    const float* K = (const float*)d_in[1];
    const float* V = (const float*)d_in[2];
    const unsigned char* kpm = (const unsigned char*)d_in[3];
    const int* cls = (const int*)d_in[4];
    float* O = (float*)d_out;

    cudaFuncSetAttribute(fa_mma_kernel, cudaFuncAttributeMaxDynamicSharedMemorySize, SMEM_BYTES);
    dim3 grid(S_/BQ, B_);
    fa_mma_kernel<<<grid, NT, SMEM_BYTES>>>(Q, K, V, kpm, cls, O);
}

// round 11
// speedup vs baseline: 1.2928x; 1.2928x over previous
#include <cuda_runtime.h>
#include <cuda_bf16.h>

#define B_  16
#define S_  2048
#define D_  128
#define BQ  128
#define BK  64
#define NT  256
#define NTILES (S_/BK)

#define QSTR 528             // Q/K smem row stride bytes (128 f32 + 16 pad)
#define VSTR 272             // V^T smem row stride bytes (64 f32 + 16 pad)

#define OFF_Q   0            // 128 x 528 = 67584
#define OFF_K   67584        // 64 x 528  = 33792
#define OFF_VT  101376       // 128 x 272 = 34816
#define OFF_KPM 136192       // 64 B
#define SMEM_BYTES (136192 + 256)

__device__ __forceinline__ unsigned smem_u32(const void* p) {
    unsigned a;
    asm("{ .reg .u64 t; cvta.to.shared.u64 t, %1; cvt.u32.u64 %0, t; }" : "=r"(a) : "l"(p));
    return a;
}

#define LDSM_X4(r0,r1,r2,r3,a) \
    asm("ldmatrix.sync.aligned.m8n8.x4.shared.b16 {%0,%1,%2,%3}, [%4];" \
        : "=r"(r0),"=r"(r1),"=r"(r2),"=r"(r3) : "r"(a) : "memory")

// tf32 m16n8k8: A = 4 regs, B = 2 regs, C = 4 f32
#define MMAT(c,a0,a1,a2,a3,b0,b1) \
    asm("mma.sync.aligned.m16n8k8.row.col.f32.tf32.tf32.f32 " \
        "{%0,%1,%2,%3}, {%4,%5,%6,%7}, {%8,%9}, {%0,%1,%2,%3};" \
        : "+f"((c)[0]),"+f"((c)[1]),"+f"((c)[2]),"+f"((c)[3]) \
        : "r"(a0),"r"(a1),"r"(a2),"r"(a3),"r"(b0),"r"(b1))

#define F2TF(u, f) asm("cvt.rna.tf32.f32 %0, %1;" : "=r"(u) : "f"(f))

// cooperative load of [ROWS][128] f32 tile -> tf32-rounded smem (stride SSTR)
template<int ROWS, int SSTR>
__device__ __forceinline__ void load_tf32(char* smc, const float* g, int off, float mul) {
    const float4* g4 = reinterpret_cast<const float4*>(g);
    #pragma unroll
    for (int it = 0; it < (ROWS * 32) / NT; ++it) {
        int idx = threadIdx.x + it * NT;
        int r = idx >> 5, c4 = idx & 31;
        float4 v = g4[idx];
        unsigned w0, w1, w2, w3;
        F2TF(w0, v.x * mul); F2TF(w1, v.y * mul);
        F2TF(w2, v.z * mul); F2TF(w3, v.w * mul);
        uint4 u = make_uint4(w0, w1, w2, w3);
        *reinterpret_cast<uint4*>(smc + off + r * SSTR + c4 * 16) = u;
    }
}

// transposed V load: smem V^T[dcol][key] tf32. global reads coalesced over dcol.
__device__ __forceinline__ void load_vT(char* smc, const float* g) {
    #pragma unroll
    for (int it = 0; it < 8; ++it) {
        int idx = threadIdx.x + it * NT;
        int c  = idx & 127;        // dcol
        int r4 = idx >> 7;         // key group of 4
        unsigned w0, w1, w2, w3;
        F2TF(w0, g[(size_t)(r4*4+0)*D_ + c]);
        F2TF(w1, g[(size_t)(r4*4+1)*D_ + c]);
        F2TF(w2, g[(size_t)(r4*4+2)*D_ + c]);
        F2TF(w3, g[(size_t)(r4*4+3)*D_ + c]);
        uint4 u = make_uint4(w0, w1, w2, w3);
        *reinterpret_cast<uint4*>(smc + OFF_VT + c * VSTR + r4 * 16) = u;
    }
}

__global__ __launch_bounds__(NT, 1)
void fa_tf32_kernel(const float* __restrict__ Q, const float* __restrict__ K,
                    const float* __restrict__ V, const unsigned char* __restrict__ kpm,
                    const int* __restrict__ cls, float* __restrict__ O)
{
    extern __shared__ char smc[];
    const unsigned sb = smem_u32(smc);
    const int tid  = threadIdx.x;
    const int wid  = tid >> 5;
    const int lane = tid & 31;
    const int b  = blockIdx.y;
    const int q0 = blockIdx.x * BQ;

    const int i0 = cls[b*3 + 0];
    const int i1 = cls[b*3 + 1];
    const int i2 = cls[b*3 + 2];

    const int rg0 = q0 + wid*16 + (lane >> 2);
    const int rg1 = rg0 + 8;
    const bool isr1_0 = (rg0 == i1), isr2_0 = (rg0 == i2);
    const bool isr1_1 = (rg1 == i1), isr2_1 = (rg1 == i2);

    // Q tile -> smem (tf32-rounded, pre-scaled by 1/sqrt(d))
    load_tf32<BQ, QSTR>(smc, Q + ((size_t)b*S_ + q0)*D_, OFF_Q, 0.08838834764831845f);

    float o[16][4];
    #pragma unroll
    for (int i = 0; i < 16; ++i)
        #pragma unroll
        for (int j = 0; j < 4; ++j) o[i][j] = 0.0f;
    float lsum0 = 0.0f, lsum1 = 0.0f;

    // ldmatrix lane base addresses (byte offsets)
    // A (Q): m0 lanes0-7 rows wid*16+0-7 @k0-3 | m1 l8-15 rows+8 @k0-3 | m2 l16-23 rows0-7 @k4-7 | m3 rows+8 @k4-7
    const unsigned qbase = (unsigned)((wid*16 + (lane&7) + ((lane>>3)&1)*8) * QSTR + ((lane>>4)*4)*4);
    // B (K): m0 l0-7 keys n..n+7 @k0-3 | m1 l8-15 same keys @k4-7 | m2 l16-23 keys+8 @k0-3 | m3 keys+8 @k4-7
    const unsigned kbase = (unsigned)(((lane&7) + (lane>>4)*8) * QSTR + (((lane>>3)&1)*4)*4);
    // B (V^T): same pattern, rows are dcols, words are keys
    const unsigned vbase = (unsigned)(((lane&7) + (lane>>4)*8) * VSTR + (((lane>>3)&1)*4)*4);

    const int m_ = lane & 3;
    const unsigned src0 = (unsigned)((lane & 28) | (m_ >> 1));
    const unsigned src2 = src0 | 2u;
    const bool modd = (m_ & 1) != 0;

    for (int tl = 0; tl < NTILES; ++tl) {
        const int kb = tl * BK;
        __syncthreads();   // previous tile's K/V readers done

        load_tf32<BK, QSTR>(smc, K + ((size_t)b*S_ + kb)*D_, OFF_K, 1.0f);
        load_vT(smc, V + ((size_t)b*S_ + kb)*D_);
        if (tid < 16) ((unsigned*)(smc + OFF_KPM))[tid] = ((const unsigned*)(kpm + (size_t)b*S_ + kb))[tid];
        __syncthreads();

        // ---- QK^T : 16 rows x 64 keys, single-pass tf32 (16 k-steps of 8) ----
        float s[8][4];
        #pragma unroll
        for (int i = 0; i < 8; ++i)
            #pragma unroll
            for (int j = 0; j < 4; ++j) s[i][j] = 0.0f;

        #pragma unroll
        for (int ks = 0; ks < 16; ++ks) {
            unsigned a0, a1, a2, a3;
            LDSM_X4(a0, a1, a2, a3, sb + OFF_Q + qbase + (unsigned)(ks*32));
            #pragma unroll
            for (int np2 = 0; np2 < 4; ++np2) {   // two 8-key n-tiles per x4
                unsigned b0, b1, b2, b3;
                LDSM_X4(b0, b1, b2, b3, sb + OFF_K + (unsigned)(np2*16*QSTR) + kbase + (unsigned)(ks*32));
                MMAT(s[2*np2],   a0, a1, a2, a3, b0, b1);
                MMAT(s[2*np2+1], a0, a1, a2, a3, b2, b3);
            }
        }

        // ---- mask + exp (in place, f32) ----
        const unsigned char* kpms = (const unsigned char*)(smc + OFF_KPM);
        #pragma unroll
        for (int nt = 0; nt < 8; ++nt) {
            const int jl0 = nt*8 + m_*2;
            const int jg0 = kb + jl0, jg1 = jg0 + 1;
            const bool kp0 = kpms[jl0] != 0, kp1 = kpms[jl0 + 1] != 0;
            const bool key1_0 = ((jg0 > i1) && (jg0 <= i2)) || (jg0 == 0);
            const bool key1_1 = ((jg1 > i1) && (jg1 <= i2)) || (jg1 == 0);
            const bool key2_0 = ((jg0 > i0) && (jg0 <= i1)) || (jg0 == 0);
            const bool key2_1 = ((jg1 > i0) && (jg1 <= i1)) || (jg1 == 0);

            float v0 = (kp0 || (isr1_0 && key1_0) || (isr2_0 && key2_0)) ? -1e30f : s[nt][0];
            float v1 = (kp1 || (isr1_0 && key1_1) || (isr2_0 && key2_1)) ? -1e30f : s[nt][1];
            float v2 = (kp0 || (isr1_1 && key1_0) || (isr2_1 && key2_0)) ? -1e30f : s[nt][2];
            float v3 = (kp1 || (isr1_1 && key1_1) || (isr2_1 && key2_1)) ? -1e30f : s[nt][3];

            float p0 = __expf(fminf(v0, 60.0f));
            float p1 = __expf(fminf(v1, 60.0f));
            float p2 = __expf(fminf(v2, 60.0f));
            float p3 = __expf(fminf(v3, 60.0f));
            lsum0 += p0 + p1;
            lsum1 += p2 + p3;
            s[nt][0] = p0; s[nt][1] = p1; s[nt][2] = p2; s[nt][3] = p3;
        }

        // ---- P·V : 8 k-steps (one per score n-tile), a-frag via shfl ----
        #pragma unroll
        for (int ks = 0; ks < 8; ++ks) {
            unsigned u0, u1, u2, u3;
            F2TF(u0, s[ks][0]); F2TF(u1, s[ks][1]);
            F2TF(u2, s[ks][2]); F2TF(u3, s[ks][3]);
            // a0=(r, key m), a1=(r+8, key m), a2=(r, key m+4), a3=(r+8, key m+4)
            unsigned t00 = __shfl_sync(0xffffffffu, u0, src0);
            unsigned t01 = __shfl_sync(0xffffffffu, u1, src0);
            unsigned t20 = __shfl_sync(0xffffffffu, u2, src0);
            unsigned t21 = __shfl_sync(0xffffffffu, u3, src0);
            unsigned t02 = __shfl_sync(0xffffffffu, u0, src2);
            unsigned t03 = __shfl_sync(0xffffffffu, u1, src2);
            unsigned t22 = __shfl_sync(0xffffffffu, u2, src2);
            unsigned t23 = __shfl_sync(0xffffffffu, u3, src2);
            unsigned a0 = modd ? t01 : t00;
            unsigned a1 = modd ? t21 : t20;
            unsigned a2 = modd ? t03 : t02;
            unsigned a3 = modd ? t23 : t22;

            #pragma unroll
            for (int dp2 = 0; dp2 < 8; ++dp2) {   // two 8-dcol n-tiles per x4
                unsigned v0, v1, v2, v3;
                LDSM_X4(v0, v1, v2, v3, sb + OFF_VT + (unsigned)(dp2*16*VSTR) + vbase + (unsigned)(ks*32));
                MMAT(o[2*dp2],   a0, a1, a2, a3, v0, v1);
                MMAT(o[2*dp2+1], a0, a1, a2, a3, v2, v3);
            }
        }
    }

    // ---- final: reduce l across quad, normalize, store ----
    lsum0 += __shfl_xor_sync(0xffffffffu, lsum0, 1);
    lsum0 += __shfl_xor_sync(0xffffffffu, lsum0, 2);
    lsum1 += __shfl_xor_sync(0xffffffffu, lsum1, 1);
    lsum1 += __shfl_xor_sync(0xffffffffu, lsum1, 2);
    const float inv0 = 1.0f / lsum0;
    const float inv1 = 1.0f / lsum1;

    float* O0 = O + ((size_t)b*S_ + rg0)*D_;
    float* O1 = O + ((size_t)b*S_ + rg1)*D_;
    #pragma unroll
    for (int dt = 0; dt < 16; ++dt) {
        const int col = dt*8 + m_*2;
        float2 w0 = make_float2(o[dt][0]*inv0, o[dt][1]*inv0);
        float2 w1 = make_float2(o[dt][2]*inv1, o[dt][3]*inv1);
        *reinterpret_cast<float2*>(O0 + col) = w0;
        *reinterpret_cast<float2*>(O1 + col) = w1;
    }
}

extern "C" void kernel_launch(void* const* d_in, const int* in_sizes, int n_in,
                              void* d_out, int out_size)
{
    const float* Q = (const float*)d_in[0];
    const float* K = (const float*)d_in[1];
    const float* V = (const float*)d_in[2];
    const unsigned char* kpm = (const unsigned char*)d_in[3];
    const int* cls = (const int*)d_in[4];
    float* O = (float*)d_out;

    cudaFuncSetAttribute(fa_tf32_kernel, cudaFuncAttributeMaxDynamicSharedMemorySize, SMEM_BYTES);
    dim3 grid(S_/BQ, B_);
    fa_tf32_kernel<<<grid, NT, SMEM_BYTES>>>(Q, K, V, kpm, cls, O);
}